// round 9
// baseline (speedup 1.0000x reference)
#include <cuda_runtime.h>
#include <cuda_bf16.h>
#include <math.h>
#include <stdint.h>

typedef unsigned long long U64;
typedef unsigned int U32;

// Problem constants
#define BB   4
#define CC   128
#define HH   96
#define WW   96
#define HWX  (HH*WW)          // 9216
#define CHW  (CC*HWX)         // 1179648
#define CO   256
#define KTOT (CC*9)           // 1152
#define NIT  36               // GEMM K-iters (KC = 32)
#define NTIL 288              // pixel tiles of 128
#define ITPB 6                // gather iters per block

// Scratch (device globals)
// Bilinear params per (tile, k, pxl): packed index + 4 weights
__device__ int    g_ppi[NTIL * 9 * 128];
__device__ float4 g_ppw[NTIL * 9 * 128];
// A images: [36 it][2 coHalf][16KB: 128 o rows x (hi 64B | lo 64B), SW128]
__device__ __align__(16) unsigned char g_wtsm[NIT * 2 * 16384];
// B images: [tile][it][16KB: 128 px rows x (hi 64B | lo 64B), SW128]
__device__ __align__(16) unsigned char g_v[(size_t)NTIL * NIT * 16384];

union F2U { U64 u; float2 f; };

__device__ __forceinline__ U64 pk2(float a, float b) {
    U64 r; asm("mov.b64 %0, {%1, %2};" : "=l"(r) : "f"(a), "f"(b)); return r;
}
__device__ __forceinline__ void fma2(U64 &d, U64 a, U64 b) {
    asm("fma.rn.f32x2 %0, %1, %2, %3;" : "=l"(d) : "l"(a), "l"(b), "l"(d));
}
__device__ __forceinline__ unsigned s2u(const void* p) {
    return (unsigned)__cvta_generic_to_shared(p);
}
__device__ __forceinline__ void cpa16(unsigned dst, const void* src) {
    asm volatile("cp.async.cg.shared.global [%0], [%1], 16;" :: "r"(dst), "l"(src));
}
#define CP_COMMIT()  asm volatile("cp.async.commit_group;" ::: "memory")
#define CP_WAIT1()   asm volatile("cp.async.wait_group 1;" ::: "memory")
#define CP_WAIT0()   asm volatile("cp.async.wait_group 0;" ::: "memory")

#define LDSM4(r0, r1, r2, r3, addr) \
    asm volatile("ldmatrix.sync.aligned.m8n8.x4.shared.b16 {%0,%1,%2,%3}, [%4];" \
        : "=r"(r0), "=r"(r1), "=r"(r2), "=r"(r3) : "r"(addr))

#define MMA(d, a0, a1, a2, a3, b0, b1) \
    asm volatile("mma.sync.aligned.m16n8k16.row.col.f32.bf16.bf16.f32 " \
        "{%0,%1,%2,%3}, {%4,%5,%6,%7}, {%8,%9}, {%0,%1,%2,%3};" \
        : "+f"((d)[0]), "+f"((d)[1]), "+f"((d)[2]), "+f"((d)[3]) \
        : "r"(a0), "r"(a1), "r"(a2), "r"(a3), "r"(b0), "r"(b1))

// ---------------------------------------------------------------------------
// Kernel 0: weights -> bf16 hi/lo SW128 images, 32 kk per iter, split by coHalf
// ---------------------------------------------------------------------------
__global__ void k_wt(const float* __restrict__ w) {
    int i = blockIdx.x * 256 + threadIdx.x;          // < 73728
    int o  = i / 288;
    int r4 = (i - o * 288) * 4;
    float4 wv = *(const float4*)(w + o * KTOT + r4);
    int it  = r4 >> 5;
    int kkl = r4 & 31;
    int coHalf = o >> 7;
    int ol     = o & 127;
    unsigned imgb = (unsigned)(it * 2 + coHalf) * 16384 + (unsigned)(ol >> 3) * 1024;
    unsigned rb   = (ol & 7) * 128;
    unsigned key  = (unsigned)(ol & 7) << 4;
    const float* fv = (const float*)&wv;
    U64 hi = 0, lo = 0;
#pragma unroll
    for (int e = 0; e < 4; ++e) {
        __nv_bfloat16 h = __float2bfloat16(fv[e]);
        __nv_bfloat16 l = __float2bfloat16(fv[e] - __bfloat162float(h));
        hi |= (U64)__bfloat16_as_ushort(h) << (16 * e);
        lo |= (U64)__bfloat16_as_ushort(l) << (16 * e);
    }
    *(U64*)(g_wtsm + imgb + ((rb + kkl * 2) ^ key))      = hi;
    *(U64*)(g_wtsm + imgb + ((rb + 64 + kkl * 2) ^ key)) = lo;
}

// ---------------------------------------------------------------------------
// Kernel 1: fused offset(18)+mask(9) 3x3 conv, epilogue emits bilinear params.
// ---------------------------------------------------------------------------
__global__ void k_offmask(const float* __restrict__ x,
                          const float* __restrict__ ow, const float* __restrict__ ob,
                          const float* __restrict__ mw, const float* __restrict__ mb) {
    __shared__ U64 ws2[27 * 16 * 9];
    int tid = threadIdx.x;
    int p0  = (blockIdx.x * 128 + tid) * 2;
    int b   = p0 / HWX;
    int rem = p0 - b * HWX;
    int h   = rem / WW;
    int w0  = rem - h * WW;

    U64 acc2[27];
#pragma unroll
    for (int oc = 0; oc < 27; ++oc) {
        float bv = (oc < 18) ? ob[oc] : mb[oc - 18];
        acc2[oc] = pk2(bv, bv);
    }
    int  yoff[3]; bool yok[3];
#pragma unroll
    for (int dy = 0; dy < 3; ++dy) { int yy = h - 1 + dy; yok[dy] = (yy >= 0) && (yy < HH); yoff[dy] = yy * WW; }
    int  xoff[4]; bool xok[4];
#pragma unroll
    for (int dxx = 0; dxx < 4; ++dxx) { int xx = w0 - 1 + dxx; xok[dxx] = (xx >= 0) && (xx < WW); xoff[dxx] = xx; }

    const float* xb0 = x + b * CHW;
    float xv[3][4], xvn[3][4];
#pragma unroll
    for (int dy = 0; dy < 3; ++dy)
#pragma unroll
        for (int dxx = 0; dxx < 4; ++dxx)
            xv[dy][dxx] = (yok[dy] && xok[dxx]) ? xb0[yoff[dy] + xoff[dxx]] : 0.f;

    for (int cc = 0; cc < 8; ++cc) {
        __syncthreads();
        for (int lin = tid; lin < 3888; lin += 128) {
            int oc = lin / 144;
            int r  = lin - oc * 144;
            float wv = (oc < 18) ? ow[oc * KTOT + cc * 144 + r]
                                 : mw[(oc - 18) * KTOT + cc * 144 + r];
            ws2[lin] = pk2(wv, wv);
        }
        __syncthreads();
        for (int c16 = 0; c16 < 16; ++c16) {
            int cg = cc * 16 + c16;
            if (cg < CC - 1) {
                const float* xb = xb0 + (cg + 1) * HWX;
#pragma unroll
                for (int dy = 0; dy < 3; ++dy)
#pragma unroll
                    for (int dxx = 0; dxx < 4; ++dxx)
                        xvn[dy][dxx] = (yok[dy] && xok[dxx]) ? xb[yoff[dy] + xoff[dxx]] : 0.f;
            }
            U64 xp[9];
#pragma unroll
            for (int ky = 0; ky < 3; ++ky)
#pragma unroll
                for (int kx = 0; kx < 3; ++kx)
                    xp[ky * 3 + kx] = pk2(xv[ky][kx], xv[ky][kx + 1]);
            const U64* wp = ws2 + c16 * 9;
#pragma unroll
            for (int oc = 0; oc < 27; ++oc)
#pragma unroll
                for (int k = 0; k < 9; ++k)
                    fma2(acc2[oc], wp[oc * 144 + k], xp[k]);
#pragma unroll
            for (int dy = 0; dy < 3; ++dy)
#pragma unroll
                for (int dxx = 0; dxx < 4; ++dxx)
                    xv[dy][dxx] = xvn[dy][dxx];
        }
    }

    // ---- Epilogue: bilinear params for both pixels, all 9 kcells ----
#pragma unroll 3
    for (int k = 0; k < 9; ++k) {
        F2U dyu, dxu, mu;
        dyu.u = acc2[2 * k]; dxu.u = acc2[2 * k + 1]; mu.u = acc2[18 + k];
        float ms0 = 1.f / (1.f + expf(-mu.f.x));
        float ms1 = 1.f / (1.f + expf(-mu.f.y));
        int ky = k / 3, kx = k - ky * 3;
#pragma unroll
        for (int e = 0; e < 2; ++e) {
            float dyv = e ? dyu.f.y : dyu.f.x;
            float dxv = e ? dxu.f.y : dxu.f.x;
            float m   = e ? ms1 : ms0;
            int pg  = p0 + e;
            int w   = w0 + e;
            float py = (float)(h - 1 + ky) + dyv;
            float px = (float)(w - 1 + kx) + dxv;
            float fy = floorf(py), fxx = floorf(px);
            int y0 = (int)fy, x0 = (int)fxx;
            float ly = py - fy, lx = px - fxx;
            float hy = 1.f - ly, hx = 1.f - lx;
            bool vy0 = (y0 >= 0)  && (y0 < HH);
            bool vy1 = (y0 >= -1) && (y0 < HH - 1);
            bool vx0 = (x0 >= 0)  && (x0 < WW);
            bool vx1 = (x0 >= -1) && (x0 < WW - 1);
            int y0c = min(max(y0, 0), HH - 1), y1c = min(max(y0 + 1, 0), HH - 1);
            int x0c = min(max(x0, 0), WW - 1), x1c = min(max(x0 + 1, 0), WW - 1);
            int pi = (b * CHW + y0c * WW + x0c)
                   | ((x1c - x0c) << 23) | ((y1c - y0c) << 24);
            float4 pw;
            pw.x = (vy0 && vx0) ? hy * hx * m : 0.f;
            pw.y = (vy0 && vx1) ? hy * lx * m : 0.f;
            pw.z = (vy1 && vx0) ? ly * hx * m : 0.f;
            pw.w = (vy1 && vx1) ? ly * lx * m : 0.f;
            int idx = ((pg >> 7) * 9 + k) * 128 + (pg & 127);
            g_ppi[idx] = pi;
            g_ppw[idx] = pw;
        }
    }
}

// ---------------------------------------------------------------------------
// Kernel 2: standalone bilinear gather -> pre-swizzled bf16 B images (g_v).
//   Block: (6 iters, 1 tile). Warp writes 4 px rows x 128B contiguous.
// ---------------------------------------------------------------------------
__global__ __launch_bounds__(256) void k_gather(const float* __restrict__ x) {
    __shared__ int    spi[9 * 128];
    __shared__ float4 spw[9 * 128];
    int tid  = threadIdx.x;
    int tile = blockIdx.y;
    int it0  = blockIdx.x * ITPB;

    for (int i = tid; i < 1152; i += 256) {
        spi[i] = g_ppi[tile * 1152 + i];
        spw[i] = g_ppw[tile * 1152 + i];
    }
    __syncthreads();

    int l    = tid & 31;
    int wrp  = tid >> 5;
    int sub  = l & 7;        // 16B chunk: 0-3 hi, 4-7 lo
    int chnk = sub & 3;      // kk8 group within 32
    int half = sub >> 2;     // 0 = hi, 1 = lo

    for (int ii = 0; ii < ITPB; ++ii) {
        int it = it0 + ii;
        unsigned char* ib = g_v + ((size_t)tile * NIT + it) * 16384;
#pragma unroll 1
        for (int p = 0; p < 4; ++p) {
            int pxl = p * 32 + wrp * 4 + (l >> 3);
            U32 outv[4];
#pragma unroll
            for (int j = 0; j < 4; ++j) {
                U32 pair = 0;
#pragma unroll
                for (int s = 0; s < 2; ++s) {
                    int kk = it * 32 + chnk * 8 + 2 * j + s;
                    int c  = kk / 9;
                    int k  = kk - 9 * c;
                    int idx = k * 128 + pxl;
                    int pi  = spi[idx];
                    float4 pw = spw[idx];
                    int a0 = (pi & 0x7FFFFF) + c * HWX;
                    int fx = (pi >> 23) & 1;
                    int dy = ((pi >> 24) & 1) ? WW : 0;
                    float v = pw.x * x[a0] + pw.y * x[a0 + fx]
                            + pw.z * x[a0 + dy] + pw.w * x[a0 + dy + fx];
                    __nv_bfloat16 vh = __float2bfloat16(v);
                    __nv_bfloat16 vl = __float2bfloat16(v - __bfloat162float(vh));
                    unsigned short sel = half ? __bfloat16_as_ushort(vl)
                                              : __bfloat16_as_ushort(vh);
                    pair |= (U32)sel << (16 * s);
                }
                outv[j] = pair;
            }
            unsigned rb  = (pxl & 7) * 128;
            unsigned key = (unsigned)(pxl & 7) << 4;
            unsigned off = (unsigned)(pxl >> 3) * 1024
                         + ((rb + half * 64 + chnk * 16) ^ key);
            *(uint4*)(ib + off) = make_uint4(outv[0], outv[1], outv[2], outv[3]);
        }
    }
}

// ---------------------------------------------------------------------------
// Kernel 3: pure dense GEMM. Block 128 Co x 128 px; linear cp.async fills.
// ---------------------------------------------------------------------------
extern __shared__ __align__(1024) char smem_raw[];
#define SA0 0
#define SA1 16384
#define SB0 32768
#define SB1 49152
#define GEMM_SMEM 65536

__global__ __launch_bounds__(256, 2) void k_gemm(const float* __restrict__ bias,
                                                 float* __restrict__ out) {
    char* sb = smem_raw;
    int tid    = threadIdx.x;
    int wid    = tid >> 5;
    int lane   = tid & 31;
    int tile   = blockIdx.x;
    int coHalf = blockIdx.y;
    int pbase  = tile * 128;

    float acc[4][4][4];
#pragma unroll
    for (int a = 0; a < 4; ++a)
#pragma unroll
        for (int b2 = 0; b2 < 4; ++b2)
#pragma unroll
            for (int c = 0; c < 4; ++c) acc[a][b2][c] = 0.f;

    int m_base = (wid & 1) * 64;
    int n_base = (wid >> 1) * 32;

    int rA = m_base + (lane & 15);
    unsigned aRow = (unsigned)(rA >> 3) * 1024 + (rA & 7) * 128;
    unsigned aXor = (unsigned)(rA & 7) << 4;
    unsigned aKhi = (unsigned)(lane >> 4) * 16;
    int pB = n_base + ((lane >> 4) << 3) + (lane & 7);
    unsigned bRow = (unsigned)(pB >> 3) * 1024 + (pB & 7) * 128;
    unsigned bXor = (unsigned)(pB & 7) << 4;
    unsigned bKhi = (unsigned)((lane >> 3) & 1) * 16;

    unsigned sA = s2u(sb + SA0);
    unsigned sB = s2u(sb + SB0);
    const unsigned char* gA = g_wtsm + coHalf * 16384;
    const unsigned char* gB = g_v + (size_t)tile * NIT * 16384;

    // prime buffer 0
#pragma unroll
    for (int q = 0; q < 4; ++q) {
        cpa16(sA + tid * 64 + q * 16, gA + (size_t)tid * 64 + q * 16);
        cpa16(sB + tid * 64 + q * 16, gB + (size_t)tid * 64 + q * 16);
    }
    CP_COMMIT();

    for (int it = 0; it < NIT; ++it) {
        int cur = it & 1;
        bool pf = (it < NIT - 1);
        if (pf) {
            unsigned sAn = sA + (unsigned)(cur ^ 1) * 16384;
            unsigned sBn = sB + (unsigned)(cur ^ 1) * 16384;
            const unsigned char* gAn = gA + (size_t)(it + 1) * 32768;
            const unsigned char* gBn = gB + (size_t)(it + 1) * 16384;
#pragma unroll
            for (int q = 0; q < 4; ++q) {
                cpa16(sAn + tid * 64 + q * 16, gAn + (size_t)tid * 64 + q * 16);
                cpa16(sBn + tid * 64 + q * 16, gBn + (size_t)tid * 64 + q * 16);
            }
            CP_COMMIT();
            CP_WAIT1();
        } else {
            CP_WAIT0();
        }
        __syncthreads();

        unsigned sAc = sA + (unsigned)cur * 16384;
        unsigned sBc = sB + (unsigned)cur * 16384;
#pragma unroll
        for (int k16 = 0; k16 < 2; ++k16) {
            unsigned kb = (unsigned)k16 * 32;
            unsigned bOffH = bRow + ((kb + bKhi) ^ bXor);
            unsigned bOffL = bRow + ((64 + kb + bKhi) ^ bXor);
            unsigned bh[8], bl[8];
            LDSM4(bh[0], bh[1], bh[2], bh[3], sBc + bOffH);
            LDSM4(bh[4], bh[5], bh[6], bh[7], sBc + bOffH + 2048);
            LDSM4(bl[0], bl[1], bl[2], bl[3], sBc + bOffL);
            LDSM4(bl[4], bl[5], bl[6], bl[7], sBc + bOffL + 2048);
            unsigned aOffH = aRow + ((kb + aKhi) ^ aXor);
            unsigned aOffL = aRow + ((64 + kb + aKhi) ^ aXor);
#pragma unroll
            for (int mg = 0; mg < 4; ++mg) {
                unsigned a0, a1, a2, a3;
                LDSM4(a0, a1, a2, a3, sAc + aOffH + (unsigned)mg * 2048);
                MMA(acc[mg][0], a0, a1, a2, a3, bh[0], bh[1]);
                MMA(acc[mg][1], a0, a1, a2, a3, bh[2], bh[3]);
                MMA(acc[mg][2], a0, a1, a2, a3, bh[4], bh[5]);
                MMA(acc[mg][3], a0, a1, a2, a3, bh[6], bh[7]);
                MMA(acc[mg][0], a0, a1, a2, a3, bl[0], bl[1]);
                MMA(acc[mg][1], a0, a1, a2, a3, bl[2], bl[3]);
                MMA(acc[mg][2], a0, a1, a2, a3, bl[4], bl[5]);
                MMA(acc[mg][3], a0, a1, a2, a3, bl[6], bl[7]);
                LDSM4(a0, a1, a2, a3, sAc + aOffL + (unsigned)mg * 2048);
                MMA(acc[mg][0], a0, a1, a2, a3, bh[0], bh[1]);
                MMA(acc[mg][1], a0, a1, a2, a3, bh[2], bh[3]);
                MMA(acc[mg][2], a0, a1, a2, a3, bh[4], bh[5]);
                MMA(acc[mg][3], a0, a1, a2, a3, bh[6], bh[7]);
            }
        }
        __syncthreads();
    }

    // Epilogue: bias + direct stores
    int bI  = pbase / HWX;
    int rem = pbase - bI * HWX;
#pragma unroll
    for (int mg = 0; mg < 4; ++mg) {
        int o0 = coHalf * 128 + m_base + mg * 16 + (lane >> 2);
        float bv0 = bias[o0];
        float bv1 = bias[o0 + 8];
        float* base0 = out + (size_t)(bI * CO + o0) * HWX + rem;
        float* base1 = base0 + (size_t)8 * HWX;
#pragma unroll
        for (int ng = 0; ng < 4; ++ng) {
            int c = n_base + ng * 8 + (lane & 3) * 2;
            *(float2*)(base0 + c) = make_float2(acc[mg][ng][0] + bv0, acc[mg][ng][1] + bv0);
            *(float2*)(base1 + c) = make_float2(acc[mg][ng][2] + bv1, acc[mg][ng][3] + bv1);
        }
    }
}

// ---------------------------------------------------------------------------
extern "C" void kernel_launch(void* const* d_in, const int* in_sizes, int n_in,
                              void* d_out, int out_size) {
    const float* x      = (const float*)d_in[0];
    const float* weight = (const float*)d_in[1];
    const float* bias   = (const float*)d_in[2];
    const float* ow     = (const float*)d_in[3];
    const float* ob     = (const float*)d_in[4];
    const float* mw     = (const float*)d_in[5];
    const float* mb     = (const float*)d_in[6];
    float* out = (float*)d_out;

    cudaFuncSetAttribute(k_gemm, cudaFuncAttributeMaxDynamicSharedMemorySize,
                         GEMM_SMEM);

    k_wt<<<288, 256>>>(weight);
    k_offmask<<<BB * HWX / 256, 128>>>(x, ow, ob, mw, mb);
    dim3 ggrid(NIT / ITPB, NTIL);
    k_gather<<<ggrid, 256>>>(x);
    dim3 mgrid(NTIL, 2);
    k_gemm<<<mgrid, 256, GEMM_SMEM>>>(bias, out);
}

// round 10
// speedup vs baseline: 1.5926x; 1.5926x over previous
#include <cuda_runtime.h>
#include <cuda_bf16.h>
#include <math.h>
#include <stdint.h>

typedef unsigned long long U64;
typedef unsigned int U32;

// Problem constants
#define BB   4
#define CC   128
#define HH   96
#define WW   96
#define HWX  (HH*WW)          // 9216
#define CHW  (CC*HWX)         // 1179648
#define CO   256
#define KTOT (CC*9)           // 1152
#define NIT  36               // GEMM K-iters (KC = 32)
#define NTIL 288              // pixel tiles of 128

// B image: per (tile, it): hi 32 rows x 272B, then lo 32 rows x 272B
#define BROW 272
#define BIMG (2*32*BROW)      // 17408

// Scratch (device globals)
__device__ int    g_ppi[NTIL * 9 * 128];
__device__ float4 g_ppw[NTIL * 9 * 128];
// A images: [36 it][2 coHalf][16KB: 128 o rows x (hi 64B | lo 64B), SW128]
__device__ __align__(16) unsigned char g_wtsm[NIT * 2 * 16384];
// B images: [tile][it][BIMG], kk-major rows
__device__ __align__(16) unsigned char g_v[(size_t)NTIL * NIT * BIMG];

union F2U { U64 u; float2 f; };

__device__ __forceinline__ U64 pk2(float a, float b) {
    U64 r; asm("mov.b64 %0, {%1, %2};" : "=l"(r) : "f"(a), "f"(b)); return r;
}
__device__ __forceinline__ void fma2(U64 &d, U64 a, U64 b) {
    asm("fma.rn.f32x2 %0, %1, %2, %3;" : "=l"(d) : "l"(a), "l"(b), "l"(d));
}
__device__ __forceinline__ unsigned s2u(const void* p) {
    return (unsigned)__cvta_generic_to_shared(p);
}
__device__ __forceinline__ void cpa16(unsigned dst, const void* src) {
    asm volatile("cp.async.cg.shared.global [%0], [%1], 16;" :: "r"(dst), "l"(src));
}
#define CP_COMMIT()  asm volatile("cp.async.commit_group;" ::: "memory")
#define CP_WAIT1()   asm volatile("cp.async.wait_group 1;" ::: "memory")
#define CP_WAIT0()   asm volatile("cp.async.wait_group 0;" ::: "memory")

#define LDSM4(r0, r1, r2, r3, addr) \
    asm volatile("ldmatrix.sync.aligned.m8n8.x4.shared.b16 {%0,%1,%2,%3}, [%4];" \
        : "=r"(r0), "=r"(r1), "=r"(r2), "=r"(r3) : "r"(addr))
#define LDSM4T(r0, r1, r2, r3, addr) \
    asm volatile("ldmatrix.sync.aligned.m8n8.x4.trans.shared.b16 {%0,%1,%2,%3}, [%4];" \
        : "=r"(r0), "=r"(r1), "=r"(r2), "=r"(r3) : "r"(addr))

#define MMA(d, a0, a1, a2, a3, b0, b1) \
    asm volatile("mma.sync.aligned.m16n8k16.row.col.f32.bf16.bf16.f32 " \
        "{%0,%1,%2,%3}, {%4,%5,%6,%7}, {%8,%9}, {%0,%1,%2,%3};" \
        : "+f"((d)[0]), "+f"((d)[1]), "+f"((d)[2]), "+f"((d)[3]) \
        : "r"(a0), "r"(a1), "r"(a2), "r"(a3), "r"(b0), "r"(b1))

// ---------------------------------------------------------------------------
// Kernel 0: weights -> bf16 hi/lo SW128 images (A side; unchanged, validated)
// ---------------------------------------------------------------------------
__global__ void k_wt(const float* __restrict__ w) {
    int i = blockIdx.x * 256 + threadIdx.x;          // < 73728
    int o  = i / 288;
    int r4 = (i - o * 288) * 4;
    float4 wv = *(const float4*)(w + o * KTOT + r4);
    int it  = r4 >> 5;
    int kkl = r4 & 31;
    int coHalf = o >> 7;
    int ol     = o & 127;
    unsigned imgb = (unsigned)(it * 2 + coHalf) * 16384 + (unsigned)(ol >> 3) * 1024;
    unsigned rb   = (ol & 7) * 128;
    unsigned key  = (unsigned)(ol & 7) << 4;
    const float* fv = (const float*)&wv;
    U64 hi = 0, lo = 0;
#pragma unroll
    for (int e = 0; e < 4; ++e) {
        __nv_bfloat16 h = __float2bfloat16(fv[e]);
        __nv_bfloat16 l = __float2bfloat16(fv[e] - __bfloat162float(h));
        hi |= (U64)__bfloat16_as_ushort(h) << (16 * e);
        lo |= (U64)__bfloat16_as_ushort(l) << (16 * e);
    }
    *(U64*)(g_wtsm + imgb + ((rb + kkl * 2) ^ key))      = hi;
    *(U64*)(g_wtsm + imgb + ((rb + 64 + kkl * 2) ^ key)) = lo;
}

// ---------------------------------------------------------------------------
// Kernel 1: fused offset(18)+mask(9) conv -> bilinear params (unchanged)
// ---------------------------------------------------------------------------
__global__ void k_offmask(const float* __restrict__ x,
                          const float* __restrict__ ow, const float* __restrict__ ob,
                          const float* __restrict__ mw, const float* __restrict__ mb) {
    __shared__ U64 ws2[27 * 16 * 9];
    int tid = threadIdx.x;
    int p0  = (blockIdx.x * 128 + tid) * 2;
    int b   = p0 / HWX;
    int rem = p0 - b * HWX;
    int h   = rem / WW;
    int w0  = rem - h * WW;

    U64 acc2[27];
#pragma unroll
    for (int oc = 0; oc < 27; ++oc) {
        float bv = (oc < 18) ? ob[oc] : mb[oc - 18];
        acc2[oc] = pk2(bv, bv);
    }
    int  yoff[3]; bool yok[3];
#pragma unroll
    for (int dy = 0; dy < 3; ++dy) { int yy = h - 1 + dy; yok[dy] = (yy >= 0) && (yy < HH); yoff[dy] = yy * WW; }
    int  xoff[4]; bool xok[4];
#pragma unroll
    for (int dxx = 0; dxx < 4; ++dxx) { int xx = w0 - 1 + dxx; xok[dxx] = (xx >= 0) && (xx < WW); xoff[dxx] = xx; }

    const float* xb0 = x + b * CHW;
    float xv[3][4], xvn[3][4];
#pragma unroll
    for (int dy = 0; dy < 3; ++dy)
#pragma unroll
        for (int dxx = 0; dxx < 4; ++dxx)
            xv[dy][dxx] = (yok[dy] && xok[dxx]) ? xb0[yoff[dy] + xoff[dxx]] : 0.f;

    for (int cc = 0; cc < 8; ++cc) {
        __syncthreads();
        for (int lin = tid; lin < 3888; lin += 128) {
            int oc = lin / 144;
            int r  = lin - oc * 144;
            float wv = (oc < 18) ? ow[oc * KTOT + cc * 144 + r]
                                 : mw[(oc - 18) * KTOT + cc * 144 + r];
            ws2[lin] = pk2(wv, wv);
        }
        __syncthreads();
        for (int c16 = 0; c16 < 16; ++c16) {
            int cg = cc * 16 + c16;
            if (cg < CC - 1) {
                const float* xb = xb0 + (cg + 1) * HWX;
#pragma unroll
                for (int dy = 0; dy < 3; ++dy)
#pragma unroll
                    for (int dxx = 0; dxx < 4; ++dxx)
                        xvn[dy][dxx] = (yok[dy] && xok[dxx]) ? xb[yoff[dy] + xoff[dxx]] : 0.f;
            }
            U64 xp[9];
#pragma unroll
            for (int ky = 0; ky < 3; ++ky)
#pragma unroll
                for (int kx = 0; kx < 3; ++kx)
                    xp[ky * 3 + kx] = pk2(xv[ky][kx], xv[ky][kx + 1]);
            const U64* wp = ws2 + c16 * 9;
#pragma unroll
            for (int oc = 0; oc < 27; ++oc)
#pragma unroll
                for (int k = 0; k < 9; ++k)
                    fma2(acc2[oc], wp[oc * 144 + k], xp[k]);
#pragma unroll
            for (int dy = 0; dy < 3; ++dy)
#pragma unroll
                for (int dxx = 0; dxx < 4; ++dxx)
                    xv[dy][dxx] = xvn[dy][dxx];
        }
    }

#pragma unroll 3
    for (int k = 0; k < 9; ++k) {
        F2U dyu, dxu, mu;
        dyu.u = acc2[2 * k]; dxu.u = acc2[2 * k + 1]; mu.u = acc2[18 + k];
        float ms0 = 1.f / (1.f + expf(-mu.f.x));
        float ms1 = 1.f / (1.f + expf(-mu.f.y));
        int ky = k / 3, kx = k - ky * 3;
#pragma unroll
        for (int e = 0; e < 2; ++e) {
            float dyv = e ? dyu.f.y : dyu.f.x;
            float dxv = e ? dxu.f.y : dxu.f.x;
            float m   = e ? ms1 : ms0;
            int pg  = p0 + e;
            int w   = w0 + e;
            float py = (float)(h - 1 + ky) + dyv;
            float px = (float)(w - 1 + kx) + dxv;
            float fy = floorf(py), fxx = floorf(px);
            int y0 = (int)fy, x0 = (int)fxx;
            float ly = py - fy, lx = px - fxx;
            float hy = 1.f - ly, hx = 1.f - lx;
            bool vy0 = (y0 >= 0)  && (y0 < HH);
            bool vy1 = (y0 >= -1) && (y0 < HH - 1);
            bool vx0 = (x0 >= 0)  && (x0 < WW);
            bool vx1 = (x0 >= -1) && (x0 < WW - 1);
            int y0c = min(max(y0, 0), HH - 1), y1c = min(max(y0 + 1, 0), HH - 1);
            int x0c = min(max(x0, 0), WW - 1), x1c = min(max(x0 + 1, 0), WW - 1);
            int pi = (b * CHW + y0c * WW + x0c)
                   | ((x1c - x0c) << 23) | ((y1c - y0c) << 24);
            float4 pw;
            pw.x = (vy0 && vx0) ? hy * hx * m : 0.f;
            pw.y = (vy0 && vx1) ? hy * lx * m : 0.f;
            pw.z = (vy1 && vx0) ? ly * hx * m : 0.f;
            pw.w = (vy1 && vx1) ? ly * lx * m : 0.f;
            int idx = ((pg >> 7) * 9 + k) * 128 + (pg & 127);
            g_ppi[idx] = pi;
            g_ppw[idx] = pw;
        }
    }
}

// ---------------------------------------------------------------------------
// Kernel 2: bilinear gather. Warp = one kk x 128 px (lane -> px {l,+32,+64,+96}).
//   Coalesced taps, single hi/lo computation, kk-major row stores.
// ---------------------------------------------------------------------------
__global__ __launch_bounds__(256) void k_gather(const float* __restrict__ x) {
    __shared__ int    spi[9 * 128];
    __shared__ float4 spw[9 * 128];
    int tid  = threadIdx.x;
    int tile = blockIdx.y;
    int q    = blockIdx.x;          // kk quarter: 288 kk

    for (int i = tid; i < 1152; i += 256) {
        spi[i] = g_ppi[tile * 1152 + i];
        spw[i] = g_ppw[tile * 1152 + i];
    }
    __syncthreads();

    int wrp = tid >> 5, l = tid & 31;
    int kk  = q * 288 + wrp;
    int c   = kk / 9;
    int k   = kk - 9 * c;
    int coff = c * HWX;
    unsigned char* tb = g_v + (size_t)tile * NIT * BIMG;

    for (int i = 0; i < 36; ++i) {
        float xv[4][4];
#pragma unroll
        for (int e = 0; e < 4; ++e) {
            int px = e * 32 + l;
            int pi = spi[k * 128 + px];
            int a0 = (pi & 0x7FFFFF) + coff;
            int fx = (pi >> 23) & 1;
            int dy = ((pi >> 24) & 1) ? WW : 0;
            xv[e][0] = x[a0];
            xv[e][1] = x[a0 + fx];
            xv[e][2] = x[a0 + dy];
            xv[e][3] = x[a0 + dy + fx];
        }
        unsigned char* rowh = tb + (size_t)(kk >> 5) * BIMG + (kk & 31) * BROW;
        unsigned char* rowl = rowh + 32 * BROW;
#pragma unroll
        for (int e = 0; e < 4; ++e) {
            int px = e * 32 + l;
            float4 pw = spw[k * 128 + px];
            float v = pw.x * xv[e][0] + pw.y * xv[e][1]
                    + pw.z * xv[e][2] + pw.w * xv[e][3];
            __nv_bfloat16 vh = __float2bfloat16(v);
            __nv_bfloat16 vl = __float2bfloat16(v - __bfloat162float(vh));
            *(unsigned short*)(rowh + px * 2) = __bfloat16_as_ushort(vh);
            *(unsigned short*)(rowl + px * 2) = __bfloat16_as_ushort(vl);
        }
        kk += 8;
        k += 8; if (k >= 9) { k -= 9; coff += HWX; }
    }
}

// ---------------------------------------------------------------------------
// Kernel 3: pure dense GEMM. A: SW128/non-trans (validated); B: kk-major/trans.
// ---------------------------------------------------------------------------
extern __shared__ __align__(1024) char smem_raw[];
#define SA0 0
#define SB0 32768
#define GEMM_SMEM (32768 + 2*BIMG)   // 67584

__global__ __launch_bounds__(256, 2) void k_gemm(const float* __restrict__ bias,
                                                 float* __restrict__ out) {
    char* sb = smem_raw;
    int tid    = threadIdx.x;
    int wid    = tid >> 5;
    int lane   = tid & 31;
    int coHalf = blockIdx.x;
    int tile   = blockIdx.y;
    int pbase  = tile * 128;

    float acc[4][4][4];
#pragma unroll
    for (int a = 0; a < 4; ++a)
#pragma unroll
        for (int b2 = 0; b2 < 4; ++b2)
#pragma unroll
            for (int c = 0; c < 4; ++c) acc[a][b2][c] = 0.f;

    int m_base = (wid & 1) * 64;
    int n_base = (wid >> 1) * 32;

    // A ldmatrix addressing (non-trans, SW128)
    int rA = m_base + (lane & 15);
    unsigned aRow = (unsigned)(rA >> 3) * 1024 + (rA & 7) * 128;
    unsigned aXor = (unsigned)(rA & 7) << 4;
    unsigned aKhi = (unsigned)(lane >> 4) * 16;
    // B ldmatrix.trans addressing (kk-major rows, 272B pitch)
    unsigned rB   = (unsigned)(lane & 15);
    unsigned colb = (unsigned)n_base * 2 + (unsigned)(lane >> 4) * 16;
    unsigned bBase = rB * BROW + colb;

    unsigned sA = s2u(sb + SA0);
    unsigned sB = s2u(sb + SB0);
    const unsigned char* gA = g_wtsm + coHalf * 16384;
    const unsigned char* gB = g_v + (size_t)tile * NIT * BIMG;

    // prime buffer 0
#pragma unroll
    for (int q = 0; q < 4; ++q)
        cpa16(sA + tid * 64 + q * 16, gA + (size_t)tid * 64 + q * 16);
#pragma unroll
    for (int q = 0; q < 5; ++q) {
        int ch = q * 256 + tid;
        if (ch < BIMG / 16) cpa16(sB + ch * 16, gB + (size_t)ch * 16);
    }
    CP_COMMIT();

    for (int it = 0; it < NIT; ++it) {
        int cur = it & 1;
        bool pf = (it < NIT - 1);
        if (pf) {
            unsigned sAn = sA + (unsigned)(cur ^ 1) * 16384;
            unsigned sBn = sB + (unsigned)(cur ^ 1) * BIMG;
            const unsigned char* gAn = gA + (size_t)(it + 1) * 32768;
            const unsigned char* gBn = gB + (size_t)(it + 1) * BIMG;
#pragma unroll
            for (int q = 0; q < 4; ++q)
                cpa16(sAn + tid * 64 + q * 16, gAn + (size_t)tid * 64 + q * 16);
#pragma unroll
            for (int q = 0; q < 5; ++q) {
                int ch = q * 256 + tid;
                if (ch < BIMG / 16) cpa16(sBn + ch * 16, gBn + (size_t)ch * 16);
            }
            CP_COMMIT();
            CP_WAIT1();
        } else {
            CP_WAIT0();
        }
        __syncthreads();

        unsigned sAc = sA + (unsigned)cur * 16384;
        unsigned sBc = sB + (unsigned)cur * BIMG;
#pragma unroll
        for (int k16 = 0; k16 < 2; ++k16) {
            unsigned kb = (unsigned)k16 * 32;
            unsigned bOffH = bBase + (unsigned)k16 * 16 * BROW;
            unsigned bOffL = bOffH + 32 * BROW;
            unsigned bh[8], bl[8];
            LDSM4T(bh[0], bh[1], bh[2], bh[3], sBc + bOffH);
            LDSM4T(bh[4], bh[5], bh[6], bh[7], sBc + bOffH + 32);
            LDSM4T(bl[0], bl[1], bl[2], bl[3], sBc + bOffL);
            LDSM4T(bl[4], bl[5], bl[6], bl[7], sBc + bOffL + 32);
            unsigned aOffH = aRow + ((kb + aKhi) ^ aXor);
            unsigned aOffL = aRow + ((64 + kb + aKhi) ^ aXor);
#pragma unroll
            for (int mg = 0; mg < 4; ++mg) {
                unsigned a0, a1, a2, a3;
                LDSM4(a0, a1, a2, a3, sAc + aOffH + (unsigned)mg * 2048);
                MMA(acc[mg][0], a0, a1, a2, a3, bh[0], bh[1]);
                MMA(acc[mg][1], a0, a1, a2, a3, bh[2], bh[3]);
                MMA(acc[mg][2], a0, a1, a2, a3, bh[4], bh[5]);
                MMA(acc[mg][3], a0, a1, a2, a3, bh[6], bh[7]);
                MMA(acc[mg][0], a0, a1, a2, a3, bl[0], bl[1]);
                MMA(acc[mg][1], a0, a1, a2, a3, bl[2], bl[3]);
                MMA(acc[mg][2], a0, a1, a2, a3, bl[4], bl[5]);
                MMA(acc[mg][3], a0, a1, a2, a3, bl[6], bl[7]);
                LDSM4(a0, a1, a2, a3, sAc + aOffL + (unsigned)mg * 2048);
                MMA(acc[mg][0], a0, a1, a2, a3, bh[0], bh[1]);
                MMA(acc[mg][1], a0, a1, a2, a3, bh[2], bh[3]);
                MMA(acc[mg][2], a0, a1, a2, a3, bh[4], bh[5]);
                MMA(acc[mg][3], a0, a1, a2, a3, bh[6], bh[7]);
            }
        }
        __syncthreads();
    }

    // Epilogue: bias + direct stores
    int bI  = pbase / HWX;
    int rem = pbase - bI * HWX;
#pragma unroll
    for (int mg = 0; mg < 4; ++mg) {
        int o0 = coHalf * 128 + m_base + mg * 16 + (lane >> 2);
        float bv0 = bias[o0];
        float bv1 = bias[o0 + 8];
        float* base0 = out + (size_t)(bI * CO + o0) * HWX + rem;
        float* base1 = base0 + (size_t)8 * HWX;
#pragma unroll
        for (int ng = 0; ng < 4; ++ng) {
            int c = n_base + ng * 8 + (lane & 3) * 2;
            *(float2*)(base0 + c) = make_float2(acc[mg][ng][0] + bv0, acc[mg][ng][1] + bv0);
            *(float2*)(base1 + c) = make_float2(acc[mg][ng][2] + bv1, acc[mg][ng][3] + bv1);
        }
    }
}

// ncu slot shifter: with 5 launches, slot 3 lands on k_gather.
__global__ void k_nop() {}

// ---------------------------------------------------------------------------
extern "C" void kernel_launch(void* const* d_in, const int* in_sizes, int n_in,
                              void* d_out, int out_size) {
    const float* x      = (const float*)d_in[0];
    const float* weight = (const float*)d_in[1];
    const float* bias   = (const float*)d_in[2];
    const float* ow     = (const float*)d_in[3];
    const float* ob     = (const float*)d_in[4];
    const float* mw     = (const float*)d_in[5];
    const float* mb     = (const float*)d_in[6];
    float* out = (float*)d_out;

    cudaFuncSetAttribute(k_gemm, cudaFuncAttributeMaxDynamicSharedMemorySize,
                         GEMM_SMEM);

    k_wt<<<288, 256>>>(weight);
    k_offmask<<<BB * HWX / 256, 128>>>(x, ow, ob, mw, mb);
    k_nop<<<1, 32>>>();
    dim3 ggrid(4, NTIL);
    k_gather<<<ggrid, 256>>>(x);
    dim3 mgrid(2, NTIL);
    k_gemm<<<mgrid, 256, GEMM_SMEM>>>(bias, out);
}